// round 16
// baseline (speedup 1.0000x reference)
#include <cuda_runtime.h>
#include <cuda_fp16.h>
#include <math.h>
#include <cstdint>

#define D 128
#define MAXN 50000
#define MAXE 800000
#define BIN 96   // slots per row bin; degree ~Poisson(16), max ~40 << 96

// Feature-permuted fp16 row layout (g_hin, g_hsup):
// uint2 index l (0..31): k = l>>2, tg = l&3.
//   lo half2 = logical kpair 8k+tg     (MMA a0)
//   hi half2 = logical kpair 8k+4+tg   (MMA a2)

__device__ uint2 g_hsup[MAXN * 32];           // support fp16, permuted layout
__device__ uint2 g_hin[MAXN * 32];            // input fp16, permuted layout
__device__ int   g_cnt[MAXN];                 // zero at launch entry (zero-init; gather re-zeroes)
__device__ int2  g_edge[MAXN * BIN];          // (col, val bits), padded per-row bins
__device__ unsigned g_wt[D * (D / 2)];        // W'^T fp16 packed pairs, [n][kpair] (unpermuted)

__device__ __forceinline__ unsigned pack_f16(float a, float b) {
    __half2 h = __floats2half2_rn(a, b);
    return *(unsigned*)&h;
}

// ---------------- build: scatter + input->fp16 (permuted) + W' — one launch, 3 block ranges ----
// scatter blocks are latency-bound (issue ~2-4%); convert/W' blocks fill the idle issue slots.

__global__ void build_kernel(const int* __restrict__ row, const int* __restrict__ col,
                             const float* __restrict__ vals,
                             const float* __restrict__ input,
                             const float* __restrict__ W,
                             const float* __restrict__ lamda_p,
                             const int* __restrict__ l_p,
                             int nScat, int nConv, int N, int E) {
    int b = blockIdx.x;
    int t = threadIdx.x;
    if (b < nScat) {                      // ---- scatter into padded bins ----
        int e = b * 256 + t;
        if (e < E) {
            int r = row[e];
            int slot = atomicAdd(&g_cnt[r], 1);
            if (slot < BIN)
                g_edge[(size_t)r * BIN + slot] = make_int2(col[e], __float_as_int(vals[e]));
        }
        return;
    }
    b -= nScat;
    if (b < nConv) {                      // ---- input -> fp16 permuted ----
        int i = b * 256 + t;              // uint2 output index
        if (i < N * 32) {
            int rowi = i >> 5, l = i & 31;
            int g = l >> 2, m = l & 3;
            const float* rp = input + (size_t)rowi * D;
            float2 lo = *(const float2*)(rp + 16 * g + 2 * m);
            float2 hi = *(const float2*)(rp + 16 * g + 8 + 2 * m);
            g_hin[i] = make_uint2(pack_f16(lo.x, lo.y), pack_f16(hi.x, hi.y));
        }
        return;
    }
    b -= nConv;
    {   // ---- W' = theta*W + (1-theta)*I : 32 blocks = 128 n x 64 kpair ----
        float theta = logf(*lamda_p / (float)(*l_p) + 1.0f);
        float om = 1.0f - theta;
        int idx = b * 256 + t;
        int n  = idx & 127;
        int kp = idx >> 7;
        int k0 = 2 * kp, k1 = 2 * kp + 1;
        float v0 = theta * __ldg(&W[k0 * D + n]) + (k0 == n ? om : 0.f);
        float v1 = theta * __ldg(&W[k1 * D + n]) + (k1 == n ? om : 0.f);
        g_wt[n * (D / 2) + kp] = pack_f16(v0, v1);
    }
}

// ---------------- gather SpMM: S = (1-alpha)*A*input + alpha*h0, fp16 permuted ----------------
// Re-zeroes g_cnt[wid] after reading (restores launch-entry state; gather is sole reader).

__global__ void gather_kernel(const float* __restrict__ h0,
                              const float* __restrict__ alpha_p, int N) {
    int wid  = (blockIdx.x * blockDim.x + threadIdx.x) >> 5;
    int lane = threadIdx.x & 31;
    if (wid >= N) return;
    int cnt = g_cnt[wid];
    if (cnt > BIN) cnt = BIN;
    if (lane == 0) g_cnt[wid] = 0;
    int beg = wid * BIN;
    int end = beg + cnt;

    float ax = 0.f, ay = 0.f, az = 0.f, aw = 0.f;
    int j = beg;
    for (; j + 8 <= end; j += 8) {
        int2 e[8];
#pragma unroll
        for (int q = 0; q < 8; q++) e[q] = __ldg(&g_edge[j + q]);
        uint2 x[8];
#pragma unroll
        for (int q = 0; q < 8; q++) x[q] = __ldg(&g_hin[(size_t)e[q].x * 32 + lane]);
#pragma unroll
        for (int q = 0; q < 8; q++) {
            float v = __int_as_float(e[q].y);
            float2 f0 = __half22float2(*(__half2*)&x[q].x);
            float2 f1 = __half22float2(*(__half2*)&x[q].y);
            ax = fmaf(v, f0.x, ax);
            ay = fmaf(v, f0.y, ay);
            az = fmaf(v, f1.x, az);
            aw = fmaf(v, f1.y, aw);
        }
    }
    for (; j < end; j++) {
        int2 e = __ldg(&g_edge[j]);
        float v = __int_as_float(e.y);
        uint2 x = __ldg(&g_hin[(size_t)e.x * 32 + lane]);
        float2 f0 = __half22float2(*(__half2*)&x.x);
        float2 f1 = __half22float2(*(__half2*)&x.y);
        ax = fmaf(v, f0.x, ax);
        ay = fmaf(v, f0.y, ay);
        az = fmaf(v, f1.x, az);
        aw = fmaf(v, f1.y, aw);
    }

    float a = *alpha_p, oma = 1.f - a;
    int g = lane >> 2, m = lane & 3;
    const float* hp = h0 + (size_t)wid * D;
    float2 hlo = *(const float2*)(hp + 16 * g + 2 * m);
    float2 hhi = *(const float2*)(hp + 16 * g + 8 + 2 * m);
    float s0 = fmaf(oma, ax, a * hlo.x);
    float s1 = fmaf(oma, ay, a * hlo.y);
    float s2 = fmaf(oma, az, a * hhi.x);
    float s3 = fmaf(oma, aw, a * hhi.y);
    g_hsup[(size_t)wid * 32 + lane] = make_uint2(pack_f16(s0, s1), pack_f16(s2, s3));
}

// ---------------- HMMA GEMM: out = S @ W' — persistent, grid-stride over 64-row tiles ----------
// Block: 256 threads = 4 row-warps x 2 col-halves; warp = 16 rows x 64 cols (acc 32 regs).
// smem B: permuted uint2 (b0,b1) at index n*36 + k*4 + tg, uint stride 72 (conflict-free),
// staged ONCE per block, reused across tiles.

#define SB_U 72   // uints per n row in smem

__global__ void __launch_bounds__(256, 4) gemm_mma_kernel(float* __restrict__ out, int N) {
    __shared__ unsigned sB[D * SB_U];   // 36 KB

    int tid  = threadIdx.x;
    int lane = tid & 31;
    int w    = tid >> 5;
    int rw   = w & 3;       // row group 0..3
    int cw   = w >> 2;      // col half 0..1

    // stage + permute W' fragments once: q = kpair (0..63) -> k=q>>3, m=q&7
    for (int i = tid; i < D * (D / 2); i += 256) {
        int n = i >> 6;
        int q = i & 63;
        int k = q >> 3, m = q & 7;
        sB[n * SB_U + ((k * 4 + (m & 3)) << 1) + (m >> 2)] = g_wt[i];
    }
    __syncthreads();

    int r0 = lane >> 2;
    int tg = lane & 3;
    const uint2* sB2 = (const uint2*)sB;
    int nTiles = (N + 63) >> 6;

    for (int tile = blockIdx.x; tile < nTiles; tile += gridDim.x) {
        int rowBase = tile * 64 + rw * 16;
        int rowA = rowBase + r0;
        int rowB = rowA + 8;
        int rA = min(rowA, N - 1);
        int rB = min(rowB, N - 1);

        float acc[8][4];
#pragma unroll
        for (int nt = 0; nt < 8; nt++)
#pragma unroll
            for (int q = 0; q < 4; q++) acc[nt][q] = 0.f;

#pragma unroll
        for (int k = 0; k < 8; k++) {
            uint2 A0 = __ldg(&g_hsup[(size_t)rA * 32 + k * 4 + tg]);
            uint2 A1 = __ldg(&g_hsup[(size_t)rB * 32 + k * 4 + tg]);
#pragma unroll
            for (int nt = 0; nt < 8; nt++) {
                int n = cw * 64 + nt * 8 + r0;
                uint2 B = sB2[n * (SB_U / 2) + k * 4 + tg];
                asm volatile(
                    "mma.sync.aligned.m16n8k16.row.col.f32.f16.f16.f32 "
                    "{%0,%1,%2,%3}, {%4,%5,%6,%7}, {%8,%9}, {%0,%1,%2,%3};"
                    : "+f"(acc[nt][0]), "+f"(acc[nt][1]), "+f"(acc[nt][2]), "+f"(acc[nt][3])
                    : "r"(A0.x), "r"(A1.x), "r"(A0.y), "r"(A1.y), "r"(B.x), "r"(B.y));
            }
        }

#pragma unroll
        for (int nt = 0; nt < 8; nt++) {
            int c = cw * 64 + nt * 8 + tg * 2;
            if (rowA < N)
                *(float2*)&out[(size_t)rowA * D + c] = make_float2(acc[nt][0], acc[nt][1]);
            if (rowB < N)
                *(float2*)&out[(size_t)rowB * D + c] = make_float2(acc[nt][2], acc[nt][3]);
        }
    }
}

// ---------------- launch ----------------

extern "C" void kernel_launch(void* const* d_in, const int* in_sizes, int n_in,
                              void* d_out, int out_size) {
    const float* input  = (const float*)d_in[0];
    const float* h0     = (const float*)d_in[1];
    const float* vals   = (const float*)d_in[2];
    const float* W      = (const float*)d_in[3];
    const float* lamda  = (const float*)d_in[4];
    const float* alpha  = (const float*)d_in[5];
    const int*   row    = (const int*)d_in[6];
    const int*   col    = (const int*)d_in[7];
    const int*   l      = (const int*)d_in[8];
    float* out = (float*)d_out;

    int N = in_sizes[0] / D;
    int E = in_sizes[2];

    int nScat = (E + 255) / 256;
    int nConv = (N * 32 + 255) / 256;
    build_kernel<<<nScat + nConv + 32, 256>>>(row, col, vals, input, W, lamda, l,
                                              nScat, nConv, N, E);

    gather_kernel<<<(N * 32 + 255) / 256, 256>>>(h0, alpha, N);

    int nTiles = (N + 63) / 64;
    int grid = 4 * 148;
    if (grid > nTiles) grid = nTiles;
    gemm_mma_kernel<<<grid, 256>>>(out, N);
}

// round 17
// speedup vs baseline: 2.0155x; 2.0155x over previous
#include <cuda_runtime.h>
#include <cuda_fp16.h>
#include <math.h>
#include <cstdint>

#define D 128
#define MAXN 50000
#define MAXE 800000
#define BIN 96   // slots per row bin; degree ~Poisson(16), max ~40 << 96

// Feature-permuted fp16 row layout (g_hin, g_hsup):
// uint2 index l (0..31): k = l>>2, tg = l&3.
//   lo half2 = logical kpair 8k+tg     (MMA a0)
//   hi half2 = logical kpair 8k+4+tg   (MMA a2)

__device__ uint2 g_hsup[MAXN * 32];           // support fp16, permuted layout
__device__ uint2 g_hin[MAXN * 32];            // input fp16, permuted layout
__device__ int   g_cnt[MAXN];
__device__ int2  g_edge[MAXN * BIN];          // (col, val bits), padded per-row bins
__device__ unsigned g_wt[D * (D / 2)];        // W'^T fp16 packed pairs, [n][kpair] (unpermuted)

__device__ __forceinline__ unsigned pack_f16(float a, float b) {
    __half2 h = __floats2half2_rn(a, b);
    return *(unsigned*)&h;
}

// ---------------- zero: g_cnt = 0 (dedicated, keeps stores out of gather) ----------------

__global__ void zero_kernel(int N) {
    int i = blockIdx.x * blockDim.x + threadIdx.x;
    if (i < N) g_cnt[i] = 0;
}

// ---------------- build: scatter + input->fp16 (permuted) + W' — one launch, 3 block ranges ----
// scatter blocks are latency-bound (issue ~2-4%); convert/W' blocks fill the idle issue slots.
// (Measured 20.1us in R16 vs 16+6 serial.)

__global__ void build_kernel(const int* __restrict__ row, const int* __restrict__ col,
                             const float* __restrict__ vals,
                             const float* __restrict__ input,
                             const float* __restrict__ W,
                             const float* __restrict__ lamda_p,
                             const int* __restrict__ l_p,
                             int nScat, int nConv, int N, int E) {
    int b = blockIdx.x;
    int t = threadIdx.x;
    if (b < nScat) {                      // ---- scatter into padded bins ----
        int e = b * 256 + t;
        if (e < E) {
            int r = row[e];
            int slot = atomicAdd(&g_cnt[r], 1);
            if (slot < BIN)
                g_edge[(size_t)r * BIN + slot] = make_int2(col[e], __float_as_int(vals[e]));
        }
        return;
    }
    b -= nScat;
    if (b < nConv) {                      // ---- input -> fp16 permuted ----
        int i = b * 256 + t;              // uint2 output index
        if (i < N * 32) {
            int rowi = i >> 5, l = i & 31;
            int g = l >> 2, m = l & 3;
            const float* rp = input + (size_t)rowi * D;
            float2 lo = *(const float2*)(rp + 16 * g + 2 * m);
            float2 hi = *(const float2*)(rp + 16 * g + 8 + 2 * m);
            g_hin[i] = make_uint2(pack_f16(lo.x, lo.y), pack_f16(hi.x, hi.y));
        }
        return;
    }
    b -= nConv;
    {   // ---- W' = theta*W + (1-theta)*I : 32 blocks = 128 n x 64 kpair ----
        float theta = logf(*lamda_p / (float)(*l_p) + 1.0f);
        float om = 1.0f - theta;
        int idx = b * 256 + t;
        int n  = idx & 127;
        int kp = idx >> 7;
        int k0 = 2 * kp, k1 = 2 * kp + 1;
        float v0 = theta * __ldg(&W[k0 * D + n]) + (k0 == n ? om : 0.f);
        float v1 = theta * __ldg(&W[k1 * D + n]) + (k1 == n ? om : 0.f);
        g_wt[n * (D / 2) + kp] = pack_f16(v0, v1);
    }
}

// ---------------- gather SpMM (R15 pristine — NO stores before/inside the loop) ----------------

__global__ void gather_kernel(const float* __restrict__ h0,
                              const float* __restrict__ alpha_p, int N) {
    int wid  = (blockIdx.x * blockDim.x + threadIdx.x) >> 5;
    int lane = threadIdx.x & 31;
    if (wid >= N) return;
    int cnt = g_cnt[wid];
    if (cnt > BIN) cnt = BIN;
    int beg = wid * BIN;
    int end = beg + cnt;

    float ax = 0.f, ay = 0.f, az = 0.f, aw = 0.f;
    int j = beg;
    for (; j + 8 <= end; j += 8) {
        int2 e[8];
#pragma unroll
        for (int q = 0; q < 8; q++) e[q] = __ldg(&g_edge[j + q]);
        uint2 x[8];
#pragma unroll
        for (int q = 0; q < 8; q++) x[q] = __ldg(&g_hin[(size_t)e[q].x * 32 + lane]);
#pragma unroll
        for (int q = 0; q < 8; q++) {
            float v = __int_as_float(e[q].y);
            float2 f0 = __half22float2(*(__half2*)&x[q].x);
            float2 f1 = __half22float2(*(__half2*)&x[q].y);
            ax = fmaf(v, f0.x, ax);
            ay = fmaf(v, f0.y, ay);
            az = fmaf(v, f1.x, az);
            aw = fmaf(v, f1.y, aw);
        }
    }
    for (; j < end; j++) {
        int2 e = __ldg(&g_edge[j]);
        float v = __int_as_float(e.y);
        uint2 x = __ldg(&g_hin[(size_t)e.x * 32 + lane]);
        float2 f0 = __half22float2(*(__half2*)&x.x);
        float2 f1 = __half22float2(*(__half2*)&x.y);
        ax = fmaf(v, f0.x, ax);
        ay = fmaf(v, f0.y, ay);
        az = fmaf(v, f1.x, az);
        aw = fmaf(v, f1.y, aw);
    }

    float a = *alpha_p, oma = 1.f - a;
    int g = lane >> 2, m = lane & 3;
    const float* hp = h0 + (size_t)wid * D;
    float2 hlo = *(const float2*)(hp + 16 * g + 2 * m);
    float2 hhi = *(const float2*)(hp + 16 * g + 8 + 2 * m);
    float s0 = fmaf(oma, ax, a * hlo.x);
    float s1 = fmaf(oma, ay, a * hlo.y);
    float s2 = fmaf(oma, az, a * hhi.x);
    float s3 = fmaf(oma, aw, a * hhi.y);
    g_hsup[(size_t)wid * 32 + lane] = make_uint2(pack_f16(s0, s1), pack_f16(s2, s3));
}

// ---------------- HMMA GEMM (R15 pristine): out = S @ W' ----------------
// Block: 256 threads = 4 row-warps x 2 col-halves -> 64 rows x 128 cols.
// smem B: permuted uint2 (b0,b1) at index n*36 + k*4 + tg, uint stride 72 (conflict-free).

#define SB_U 72   // uints per n row in smem

__global__ void __launch_bounds__(256, 4) gemm_mma_kernel(float* __restrict__ out, int N) {
    __shared__ unsigned sB[D * SB_U];   // 36 KB

    int tid  = threadIdx.x;
    int lane = tid & 31;
    int w    = tid >> 5;
    int rw   = w & 3;       // row group 0..3
    int cw   = w >> 2;      // col half 0..1
    int rowBase = blockIdx.x * 64 + rw * 16;

    for (int i = tid; i < D * (D / 2); i += 256) {
        int n = i >> 6;
        int q = i & 63;
        int k = q >> 3, m = q & 7;
        sB[n * SB_U + ((k * 4 + (m & 3)) << 1) + (m >> 2)] = g_wt[i];
    }
    __syncthreads();

    int r0 = lane >> 2;
    int tg = lane & 3;

    int rowA = rowBase + r0;
    int rowB = rowA + 8;
    int rA = min(rowA, N - 1);
    int rB = min(rowB, N - 1);

    float acc[8][4];
#pragma unroll
    for (int nt = 0; nt < 8; nt++)
#pragma unroll
        for (int q = 0; q < 4; q++) acc[nt][q] = 0.f;

    const uint2* sB2 = (const uint2*)sB;

#pragma unroll
    for (int k = 0; k < 8; k++) {
        uint2 A0 = __ldg(&g_hsup[(size_t)rA * 32 + k * 4 + tg]);
        uint2 A1 = __ldg(&g_hsup[(size_t)rB * 32 + k * 4 + tg]);
#pragma unroll
        for (int nt = 0; nt < 8; nt++) {
            int n = cw * 64 + nt * 8 + r0;
            uint2 B = sB2[n * (SB_U / 2) + k * 4 + tg];
            asm volatile(
                "mma.sync.aligned.m16n8k16.row.col.f32.f16.f16.f32 "
                "{%0,%1,%2,%3}, {%4,%5,%6,%7}, {%8,%9}, {%0,%1,%2,%3};"
                : "+f"(acc[nt][0]), "+f"(acc[nt][1]), "+f"(acc[nt][2]), "+f"(acc[nt][3])
                : "r"(A0.x), "r"(A1.x), "r"(A0.y), "r"(A1.y), "r"(B.x), "r"(B.y));
        }
    }

#pragma unroll
    for (int nt = 0; nt < 8; nt++) {
        int c = cw * 64 + nt * 8 + tg * 2;
        if (rowA < N)
            *(float2*)&out[(size_t)rowA * D + c] = make_float2(acc[nt][0], acc[nt][1]);
        if (rowB < N)
            *(float2*)&out[(size_t)rowB * D + c] = make_float2(acc[nt][2], acc[nt][3]);
    }
}

// ---------------- launch ----------------

extern "C" void kernel_launch(void* const* d_in, const int* in_sizes, int n_in,
                              void* d_out, int out_size) {
    const float* input  = (const float*)d_in[0];
    const float* h0     = (const float*)d_in[1];
    const float* vals   = (const float*)d_in[2];
    const float* W      = (const float*)d_in[3];
    const float* lamda  = (const float*)d_in[4];
    const float* alpha  = (const float*)d_in[5];
    const int*   row    = (const int*)d_in[6];
    const int*   col    = (const int*)d_in[7];
    const int*   l      = (const int*)d_in[8];
    float* out = (float*)d_out;

    int N = in_sizes[0] / D;
    int E = in_sizes[2];

    zero_kernel<<<(N + 255) / 256, 256>>>(N);

    int nScat = (E + 255) / 256;
    int nConv = (N * 32 + 255) / 256;
    build_kernel<<<nScat + nConv + 32, 256>>>(row, col, vals, input, W, lamda, l,
                                              nScat, nConv, N, E);

    gather_kernel<<<(N * 32 + 255) / 256, 256>>>(h0, alpha, N);

    gemm_mma_kernel<<<(N + 63) / 64, 256>>>(out, N);
}